// round 16
// baseline (speedup 1.0000x reference)
#include <cuda_runtime.h>
#include <cuda_bf16.h>
#include <cstdint>

#define N_TOKS 2048
#define CX 768
#define NHEAD 16
#define DH 48
#define KP (CX / 2)          // 384 k-pairs per row

// ---------------- scratch (device globals; no allocation allowed) ----------
__device__ float g_q   [N_TOKS * CX];   // tf32-rounded values
__device__ float g_k   [N_TOKS * CX];
__device__ float g_v   [N_TOKS * CX];
__device__ float g_gate[N_TOKS * CX];
// packed bf16 hi/lo operands (u32 = one k-pair)
__device__ uint32_t g_ApH[N_TOKS * KP], g_ApL[N_TOKS * KP];   // layernormed x
__device__ uint32_t g_WaH[N_TOKS * KP], g_WaL[N_TOKS * KP];   // gated wa
__device__ uint32_t g_WpH[5 * KP * CX], g_WpL[5 * KP * CX];   // weights [mat][kp][n]

// ---------------- helpers ---------------------------------------------------
__device__ __forceinline__ float tf32r(float x) {
    uint32_t u;
    asm("cvt.rna.tf32.f32 %0, %1;" : "=r"(u) : "f"(x));
    return __uint_as_float(u);
}

__device__ __forceinline__ void mma8(float& c0, float& c1, float& c2, float& c3,
                                     uint32_t a0, uint32_t a1, uint32_t a2, uint32_t a3,
                                     uint32_t b0, uint32_t b1) {
    asm volatile(
        "mma.sync.aligned.m16n8k8.row.col.f32.tf32.tf32.f32 "
        "{%0,%1,%2,%3},{%4,%5,%6,%7},{%8,%9},{%0,%1,%2,%3};"
        : "+f"(c0), "+f"(c1), "+f"(c2), "+f"(c3)
        : "r"(a0), "r"(a1), "r"(a2), "r"(a3), "r"(b0), "r"(b1));
}

__device__ __forceinline__ void mma16bf(float& c0, float& c1, float& c2, float& c3,
                                        uint32_t a0, uint32_t a1, uint32_t a2, uint32_t a3,
                                        uint32_t b0, uint32_t b1) {
    asm volatile(
        "mma.sync.aligned.m16n8k16.row.col.f32.bf16.bf16.f32 "
        "{%0,%1,%2,%3},{%4,%5,%6,%7},{%8,%9},{%0,%1,%2,%3};"
        : "+f"(c0), "+f"(c1), "+f"(c2), "+f"(c3)
        : "r"(a0), "r"(a1), "r"(a2), "r"(a3), "r"(b0), "r"(b1));
}

// split (x,y) into packed-bf16 hi and lo words (lo = residual)
__device__ __forceinline__ void split2(float x, float y, uint32_t& hw, uint32_t& lw) {
    __nv_bfloat162 h2 = __floats2bfloat162_rn(x, y);
    float hx = __bfloat162float(h2.x), hy = __bfloat162float(h2.y);
    __nv_bfloat162 l2 = __floats2bfloat162_rn(x - hx, y - hy);
    hw = *reinterpret_cast<uint32_t*>(&h2);
    lw = *reinterpret_cast<uint32_t*>(&l2);
}

__device__ __forceinline__ uint32_t s2u(const void* p) {
    return (uint32_t)__cvta_generic_to_shared(p);
}
#define CP16(dst, src) \
    asm volatile("cp.async.cg.shared.global [%0], [%1], 16;" :: "r"(s2u(dst)), "l"(src))
#define CP_COMMIT() asm volatile("cp.async.commit_group;")
#define CP_WAIT(n)  asm volatile("cp.async.wait_group %0;" :: "n"(n))

// ---------------- weight pack: W[k][n] -> Wp[mat][kp][n] hi/lo --------------
__global__ void pack_w_kernel(const float* __restrict__ W0, const float* __restrict__ W1,
                              const float* __restrict__ W2, const float* __restrict__ W3,
                              const float* __restrict__ W4) {
    int mat = blockIdx.y;
    const float* W = (mat == 0) ? W0 : (mat == 1) ? W1 : (mat == 2) ? W2
                   : (mat == 3) ? W3 : W4;
    int u = blockIdx.x * 256 + threadIdx.x;     // < 384*768
    int kp = u / CX, n = u - kp * CX;
    float w0 = W[(2 * kp) * CX + n];
    float w1 = W[(2 * kp + 1) * CX + n];
    uint32_t h, l;
    split2(w0, w1, h, l);
    int o = mat * KP * CX + u;
    g_WpH[o] = h;
    g_WpL[o] = l;
}

// ---------------- LayerNorm: writes packed hi/lo directly -------------------
__global__ void ln_kernel(const float* __restrict__ x,
                          const float* __restrict__ gw,
                          const float* __restrict__ bw) {
    int row = blockIdx.x;
    int t = threadIdx.x;
    const float* xr = x + row * CX;
    float v0 = xr[t], v1 = xr[t + 256], v2 = xr[t + 512];
    float s = v0 + v1 + v2;
    float sq = v0 * v0 + v1 * v1 + v2 * v2;
    __shared__ float rs[8], rq[8];
    #pragma unroll
    for (int o = 16; o > 0; o >>= 1) {
        s  += __shfl_xor_sync(0xffffffffu, s, o);
        sq += __shfl_xor_sync(0xffffffffu, sq, o);
    }
    if ((t & 31) == 0) { rs[t >> 5] = s; rq[t >> 5] = sq; }
    __syncthreads();
    s  = rs[0] + rs[1] + rs[2] + rs[3] + rs[4] + rs[5] + rs[6] + rs[7];
    sq = rq[0] + rq[1] + rq[2] + rq[3] + rq[4] + rq[5] + rq[6] + rq[7];
    float mu  = s * (1.0f / CX);
    float inv = rsqrtf(sq * (1.0f / CX) - mu * mu + 1e-5f);
    if (t < 192) {
        float4 xv = *(const float4*)&xr[4 * t];
        float4 gv = *(const float4*)&gw[4 * t];
        float4 bv = *(const float4*)&bw[4 * t];
        float n0 = (xv.x - mu) * inv * gv.x + bv.x;
        float n1 = (xv.y - mu) * inv * gv.y + bv.y;
        float n2 = (xv.z - mu) * inv * gv.z + bv.z;
        float n3 = (xv.w - mu) * inv * gv.w + bv.w;
        uint32_t h0, l0, h1, l1;
        split2(n0, n1, h0, l0);
        split2(n2, n3, h1, l1);
        *(uint2*)&g_ApH[row * KP + 2 * t] = make_uint2(h0, h1);
        *(uint2*)&g_ApL[row * KP + 2 * t] = make_uint2(l0, l1);
    }
}

// ---------------- bf16x2 GEMM, pre-packed operands, cp.async 2-stage --------
// C[2048 x cols] = A[2048x768] @ W[768 x cols]; C ~= AhBh + AhBl + AlBh
// mode 0: A = packed xn, mats {0..3} = {Wq,Wk,Wv,Wg} (grid.x = 48)
// mode 1: A = packed wa, mat 4 = Wo, fp32 store to dst (grid.x = 12)
__global__ __launch_bounds__(128) void gemm_kernel(
    const float* __restrict__ bq, float* __restrict__ dst, int mode) {
    __shared__ uint32_t AsH[2][64 * 20], AsL[2][64 * 20];   // [row][kp] stride 20
    __shared__ uint32_t BsH[2][16 * 64], BsL[2][16 * 64];   // [kp][n]  stride 64
    const uint32_t* APh = mode ? g_WaH : g_ApH;
    const uint32_t* APl = mode ? g_WaL : g_ApL;
    int m0 = blockIdx.y * 64;
    int gn = blockIdx.x * 64;
    int sel, n0w;
    if (mode == 0) { sel = gn / CX; n0w = gn - sel * CX; }
    else           { sel = 4;       n0w = gn; }
    const uint32_t* WpH = g_WpH + (size_t)sel * KP * CX;
    const uint32_t* WpL = g_WpL + (size_t)sel * KP * CX;

    int tid = threadIdx.x;
    int wp = tid >> 5, lane = tid & 31, g = lane >> 2, tig = lane & 3;
    int wm = wp >> 1, wn = wp & 1;

    float acc[2][4][4];
    #pragma unroll
    for (int a = 0; a < 2; a++)
        #pragma unroll
        for (int b = 0; b < 4; b++)
            #pragma unroll
            for (int c = 0; c < 4; c++) acc[a][b][c] = 0.f;

    int ar0 = tid >> 2, aq0 = (tid & 3) * 4;
    int ar1 = (tid + 128) >> 2, aq1 = aq0;
    int bk0 = tid >> 4, bq0 = (tid & 15) * 4;
    int bk1 = bk0 + 8;

    auto issue = [&](int kb, int st) {
        CP16(&AsH[st][ar0 * 20 + aq0], &APh[(size_t)(m0 + ar0) * KP + kb * 16 + aq0]);
        CP16(&AsL[st][ar0 * 20 + aq0], &APl[(size_t)(m0 + ar0) * KP + kb * 16 + aq0]);
        CP16(&AsH[st][ar1 * 20 + aq1], &APh[(size_t)(m0 + ar1) * KP + kb * 16 + aq1]);
        CP16(&AsL[st][ar1 * 20 + aq1], &APl[(size_t)(m0 + ar1) * KP + kb * 16 + aq1]);
        CP16(&BsH[st][bk0 * 64 + bq0], &WpH[(size_t)(kb * 16 + bk0) * CX + n0w + bq0]);
        CP16(&BsL[st][bk0 * 64 + bq0], &WpL[(size_t)(kb * 16 + bk0) * CX + n0w + bq0]);
        CP16(&BsH[st][bk1 * 64 + bq0], &WpH[(size_t)(kb * 16 + bk1) * CX + n0w + bq0]);
        CP16(&BsL[st][bk1 * 64 + bq0], &WpL[(size_t)(kb * 16 + bk1) * CX + n0w + bq0]);
    };

    issue(0, 0);
    CP_COMMIT();
    for (int kb = 0; kb < 24; kb++) {
        int st = kb & 1;
        if (kb < 23) { issue(kb + 1, st ^ 1); CP_COMMIT(); CP_WAIT(1); }
        else         { CP_WAIT(0); }
        __syncthreads();
        #pragma unroll
        for (int ch = 0; ch < 2; ch++) {
            int base = ch * 8;
            uint32_t ah[2][4], al[2][4];
            #pragma unroll
            for (int mt = 0; mt < 2; mt++) {
                int rr = 32 * wm + 16 * mt + g;
                int o0 = rr * 20 + base + tig;
                int o1 = (rr + 8) * 20 + base + tig;
                ah[mt][0] = AsH[st][o0];     ah[mt][1] = AsH[st][o1];
                ah[mt][2] = AsH[st][o0 + 4]; ah[mt][3] = AsH[st][o1 + 4];
                al[mt][0] = AsL[st][o0];     al[mt][1] = AsL[st][o1];
                al[mt][2] = AsL[st][o0 + 4]; al[mt][3] = AsL[st][o1 + 4];
            }
            #pragma unroll
            for (int nt = 0; nt < 4; nt++) {
                int n = 32 * wn + 8 * nt + g;
                int p0 = (base + tig) * 64 + n;
                int p1 = (base + tig + 4) * 64 + n;
                uint32_t bh0 = BsH[st][p0], bh1 = BsH[st][p1];
                uint32_t bl0 = BsL[st][p0], bl1 = BsL[st][p1];
                #pragma unroll
                for (int mt = 0; mt < 2; mt++) {
                    mma16bf(acc[mt][nt][0], acc[mt][nt][1], acc[mt][nt][2], acc[mt][nt][3],
                            ah[mt][0], ah[mt][1], ah[mt][2], ah[mt][3], bl0, bl1);
                    mma16bf(acc[mt][nt][0], acc[mt][nt][1], acc[mt][nt][2], acc[mt][nt][3],
                            al[mt][0], al[mt][1], al[mt][2], al[mt][3], bh0, bh1);
                    mma16bf(acc[mt][nt][0], acc[mt][nt][1], acc[mt][nt][2], acc[mt][nt][3],
                            ah[mt][0], ah[mt][1], ah[mt][2], ah[mt][3], bh0, bh1);
                }
            }
        }
        __syncthreads();
    }
    const float qscale = 0.14433756729740643f;  // 48^-0.5
    #pragma unroll
    for (int mt = 0; mt < 2; mt++) {
        #pragma unroll
        for (int nt = 0; nt < 4; nt++) {
            int r0 = m0 + 32 * wm + 16 * mt + g;
            int cw = n0w + 32 * wn + 8 * nt + 2 * tig;
            #pragma unroll
            for (int i = 0; i < 4; i++) {
                int row = r0 + ((i >= 2) ? 8 : 0);
                int col = cw + (i & 1);
                float v = acc[mt][nt][i];
                if (sel == 4)      dst[row * CX + col] = v;
                else if (sel == 0) g_q[row * CX + col] = tf32r((v + bq[col]) * qscale);
                else if (sel == 1) g_k[row * CX + col] = tf32r(v);
                else if (sel == 2) g_v[row * CX + col] = tf32r(v);
                else               g_gate[row * CX + col] = 1.f / (1.f + __expf(-v));
            }
        }
    }
}

// ---------------- attention: block = (64 queries) x (1 head) ---------------
// 4 warps x 16 q-rows, 32-key double-buffered tiles, fixed-max softmax.
// Pair bias double-buffered in REGISTERS (pf): tile kt+1's LDGs issue at the
// top of tile kt's body, hiding DRAM latency under the full tile.
// R16: launch_bounds min-blocks relaxed 4 -> 3 so ptxas gets ~170 regs and
// pf stays in registers (R15's cap of 128 forced spills, poisoning the test).
__global__ __launch_bounds__(128, 3) void attn_kernel(const float* __restrict__ pair,
                                                      float* __restrict__ out_wa) {
    __shared__ float Ks[2][32 * 52];
    __shared__ float Vs[2][32 * 56];
    __shared__ float Ps[64 * 36];
    int qt = blockIdx.x, h = blockIdx.y;
    int q0 = qt * 64, hc0 = h * DH;
    int tid = threadIdx.x, w = tid >> 5, lane = tid & 31, g = lane >> 2, tig = lane & 3;

    // stage Q (64x48, stride 52) through the Ks region; lift A-fragments
    float* Qstage = &Ks[0][0];   // 2*32*52 = 64*52 floats
    #pragma unroll
    for (int i = 0; i < 6; i++) {
        int f4 = tid + i * 128;
        int r = f4 / 12, c4 = f4 % 12;
        *(float4*)&Qstage[r * 52 + c4 * 4] =
            *(const float4*)&g_q[(size_t)(q0 + r) * CX + hc0 + c4 * 4];
    }
    __syncthreads();
    uint32_t qa[6][4];
    int qrow = 16 * w + g;
    #pragma unroll
    for (int ks = 0; ks < 6; ks++) {
        qa[ks][0] = __float_as_uint(Qstage[qrow * 52 + ks * 8 + tig]);
        qa[ks][1] = __float_as_uint(Qstage[(qrow + 8) * 52 + ks * 8 + tig]);
        qa[ks][2] = __float_as_uint(Qstage[qrow * 52 + ks * 8 + tig + 4]);
        qa[ks][3] = __float_as_uint(Qstage[(qrow + 8) * 52 + ks * 8 + tig + 4]);
    }
    __syncthreads();

    float l0 = 0.f, l1 = 0.f;
    float o[6][4];
    #pragma unroll
    for (int d = 0; d < 6; d++)
        #pragma unroll
        for (int i = 0; i < 4; i++) o[d][i] = 0.f;

    const float* ph = pair + (size_t)h * N_TOKS * N_TOKS;

    auto issueKV = [&](int kt, int st) {
        int k0 = kt * 32;
        #pragma unroll
        for (int i = 0; i < 3; i++) {
            int f4 = tid + i * 128;
            int r = f4 / 12, c4 = f4 % 12;
            CP16(&Ks[st][r * 52 + c4 * 4], &g_k[(size_t)(k0 + r) * CX + hc0 + c4 * 4]);
            CP16(&Vs[st][r * 56 + c4 * 4], &g_v[(size_t)(k0 + r) * CX + hc0 + c4 * 4]);
        }
    };

    // pair-bias register prefetch buffer: [nt] = {row qrow, row qrow+8}
    float2 pf[8];
    auto load_pair = [&](int kt) {
        int k0 = kt * 32;
        #pragma unroll
        for (int nt = 0; nt < 4; nt++) {
            pf[2 * nt]     = *(const float2*)&ph[(size_t)(q0 + qrow) * N_TOKS + k0 + 8 * nt + 2 * tig];
            pf[2 * nt + 1] = *(const float2*)&ph[(size_t)(q0 + qrow + 8) * N_TOKS + k0 + 8 * nt + 2 * tig];
        }
    };

    load_pair(0);
    issueKV(0, 0);
    CP_COMMIT();

    for (int kt = 0; kt < 64; kt++) {
        int st = kt & 1;

        // consume prefetched pair into S accumulators, then immediately issue
        // the NEXT tile's pair LDGs (they have the whole tile body to land)
        float s[4][4];
        #pragma unroll
        for (int nt = 0; nt < 4; nt++) {
            s[nt][0] = pf[2 * nt].x;     s[nt][1] = pf[2 * nt].y;
            s[nt][2] = pf[2 * nt + 1].x; s[nt][3] = pf[2 * nt + 1].y;
        }
        if (kt < 63) {
            load_pair(kt + 1);
            issueKV(kt + 1, st ^ 1); CP_COMMIT(); CP_WAIT(1);
        } else {
            CP_WAIT(0);
        }
        __syncthreads();

        #pragma unroll
        for (int ks = 0; ks < 6; ks++) {
            #pragma unroll
            for (int nt = 0; nt < 4; nt++) {
                uint32_t b0 = __float_as_uint(Ks[st][(8 * nt + g) * 52 + ks * 8 + tig]);
                uint32_t b1 = __float_as_uint(Ks[st][(8 * nt + g) * 52 + ks * 8 + tig + 4]);
                mma8(s[nt][0], s[nt][1], s[nt][2], s[nt][3],
                     qa[ks][0], qa[ks][1], qa[ks][2], qa[ks][3], b0, b1);
            }
        }

        // fixed-max softmax: logits = pair + scaled qk, bounded << 18
        float ls0 = 0.f, ls1 = 0.f;
        #pragma unroll
        for (int nt = 0; nt < 4; nt++) {
            float p00 = __expf(s[nt][0] - 18.f), p01 = __expf(s[nt][1] - 18.f);
            float p10 = __expf(s[nt][2] - 18.f), p11 = __expf(s[nt][3] - 18.f);
            ls0 += p00 + p01; ls1 += p10 + p11;
            int col = 8 * nt + 2 * tig;
            *(float2*)&Ps[(16 * w + g) * 36 + col]     = make_float2(tf32r(p00), tf32r(p01));
            *(float2*)&Ps[(16 * w + g + 8) * 36 + col] = make_float2(tf32r(p10), tf32r(p11));
        }
        l0 += ls0; l1 += ls1;
        __syncwarp();

        // O += P @ V
        #pragma unroll
        for (int ks = 0; ks < 4; ks++) {
            uint32_t a0 = __float_as_uint(Ps[(16 * w + g) * 36 + ks * 8 + tig]);
            uint32_t a1 = __float_as_uint(Ps[(16 * w + g + 8) * 36 + ks * 8 + tig]);
            uint32_t a2 = __float_as_uint(Ps[(16 * w + g) * 36 + ks * 8 + tig + 4]);
            uint32_t a3 = __float_as_uint(Ps[(16 * w + g + 8) * 36 + ks * 8 + tig + 4]);
            #pragma unroll
            for (int nt = 0; nt < 6; nt++) {
                uint32_t b0 = __float_as_uint(Vs[st][(ks * 8 + tig) * 56 + 8 * nt + g]);
                uint32_t b1 = __float_as_uint(Vs[st][(ks * 8 + tig + 4) * 56 + 8 * nt + g]);
                mma8(o[nt][0], o[nt][1], o[nt][2], o[nt][3], a0, a1, a2, a3, b0, b1);
            }
        }
        __syncthreads();   // release stage st before next iteration overwrites it
    }

    // butterfly across the 4 tig-lanes gives the full-row denominator
    l0 += __shfl_xor_sync(0xffffffffu, l0, 1);
    l0 += __shfl_xor_sync(0xffffffffu, l0, 2);
    l1 += __shfl_xor_sync(0xffffffffu, l1, 1);
    l1 += __shfl_xor_sync(0xffffffffu, l1, 2);

    // epilogue: normalize, gate, write wa (fp32 out) + packed hi/lo for Wo GEMM
    float inv0 = 1.f / l0, inv1 = 1.f / l1;
    int r0 = q0 + 16 * w + g, r1 = r0 + 8;
    #pragma unroll
    for (int nt = 0; nt < 6; nt++) {
        int cw = hc0 + 8 * nt + 2 * tig;
        float2 gt0 = *(const float2*)&g_gate[r0 * CX + cw];
        float2 gt1 = *(const float2*)&g_gate[r1 * CX + cw];
        float v00 = o[nt][0] * inv0 * gt0.x;
        float v01 = o[nt][1] * inv0 * gt0.y;
        float v10 = o[nt][2] * inv1 * gt1.x;
        float v11 = o[nt][3] * inv1 * gt1.y;
        *(float2*)&out_wa[r0 * CX + cw] = make_float2(v00, v01);
        *(float2*)&out_wa[r1 * CX + cw] = make_float2(v10, v11);
        uint32_t hh, ll;
        split2(v00, v01, hh, ll);
        g_WaH[r0 * KP + (cw >> 1)] = hh;
        g_WaL[r0 * KP + (cw >> 1)] = ll;
        split2(v10, v11, hh, ll);
        g_WaH[r1 * KP + (cw >> 1)] = hh;
        g_WaL[r1 * KP + (cw >> 1)] = ll;
    }
}

// ---------------- launch -----------------------------------------------------
extern "C" void kernel_launch(void* const* d_in, const int* in_sizes, int n_in,
                              void* d_out, int out_size) {
    int ip = 2;
    for (int i = 0; i < n_in; i++)
        if (in_sizes[i] == NHEAD * N_TOKS * N_TOKS) { ip = i; break; }
    int sh = ip - 2;

    const float* x    = (const float*)d_in[0];
    const float* pair = (const float*)d_in[ip];
    const float* ln_g = (const float*)d_in[3 + sh];
    const float* ln_b = (const float*)d_in[4 + sh];
    const float* Wq   = (const float*)d_in[5 + sh];
    const float* bq   = (const float*)d_in[6 + sh];
    const float* Wk   = (const float*)d_in[7 + sh];
    const float* Wv   = (const float*)d_in[8 + sh];
    const float* Wg   = (const float*)d_in[9 + sh];
    const float* Wo   = (const float*)d_in[10 + sh];

    float* out = (float*)d_out;
    const int NC = N_TOKS * CX;
    float* wa_dst  = out;
    float* out_dst = (out_size >= 2 * NC) ? (out + NC) : out;

    pack_w_kernel<<<dim3(1152, 5), 256>>>(Wq, Wk, Wv, Wg, Wo);
    ln_kernel<<<N_TOKS, 256>>>(x, ln_g, ln_b);
    gemm_kernel<<<dim3(48, 32), 128>>>(bq, nullptr, 0);
    attn_kernel<<<dim3(32, 16), 128>>>(pair, wa_dst);
    gemm_kernel<<<dim3(12, 32), 128>>>(bq, out_dst, 1);
}

// round 17
// speedup vs baseline: 1.2193x; 1.2193x over previous
#include <cuda_runtime.h>
#include <cuda_bf16.h>
#include <cstdint>

#define N_TOKS 2048
#define CX 768
#define NHEAD 16
#define DH 48
#define KP (CX / 2)          // 384 k-pairs per row

// ---------------- scratch (device globals; no allocation allowed) ----------
__device__ float g_q   [N_TOKS * CX];   // tf32-rounded values
__device__ float g_k   [N_TOKS * CX];
__device__ float g_v   [N_TOKS * CX];
__device__ float g_gate[N_TOKS * CX];
// INTERLEAVED packed bf16 operands: [..][2] = {hi, lo} per k-pair
__device__ uint32_t g_ApHL[N_TOKS * KP * 2];      // layernormed x
__device__ uint32_t g_WaHL[N_TOKS * KP * 2];      // gated wa
__device__ uint32_t g_WpHL[5 * KP * CX * 2];      // weights [mat][kp][n][2]

// ---------------- helpers ---------------------------------------------------
__device__ __forceinline__ float tf32r(float x) {
    uint32_t u;
    asm("cvt.rna.tf32.f32 %0, %1;" : "=r"(u) : "f"(x));
    return __uint_as_float(u);
}

__device__ __forceinline__ void mma8(float& c0, float& c1, float& c2, float& c3,
                                     uint32_t a0, uint32_t a1, uint32_t a2, uint32_t a3,
                                     uint32_t b0, uint32_t b1) {
    asm volatile(
        "mma.sync.aligned.m16n8k8.row.col.f32.tf32.tf32.f32 "
        "{%0,%1,%2,%3},{%4,%5,%6,%7},{%8,%9},{%0,%1,%2,%3};"
        : "+f"(c0), "+f"(c1), "+f"(c2), "+f"(c3)
        : "r"(a0), "r"(a1), "r"(a2), "r"(a3), "r"(b0), "r"(b1));
}

__device__ __forceinline__ void mma16bf(float& c0, float& c1, float& c2, float& c3,
                                        uint32_t a0, uint32_t a1, uint32_t a2, uint32_t a3,
                                        uint32_t b0, uint32_t b1) {
    asm volatile(
        "mma.sync.aligned.m16n8k16.row.col.f32.bf16.bf16.f32 "
        "{%0,%1,%2,%3},{%4,%5,%6,%7},{%8,%9},{%0,%1,%2,%3};"
        : "+f"(c0), "+f"(c1), "+f"(c2), "+f"(c3)
        : "r"(a0), "r"(a1), "r"(a2), "r"(a3), "r"(b0), "r"(b1));
}

// split (x,y) into packed-bf16 hi and lo words (lo = residual)
__device__ __forceinline__ void split2(float x, float y, uint32_t& hw, uint32_t& lw) {
    __nv_bfloat162 h2 = __floats2bfloat162_rn(x, y);
    float hx = __bfloat162float(h2.x), hy = __bfloat162float(h2.y);
    __nv_bfloat162 l2 = __floats2bfloat162_rn(x - hx, y - hy);
    hw = *reinterpret_cast<uint32_t*>(&h2);
    lw = *reinterpret_cast<uint32_t*>(&l2);
}

__device__ __forceinline__ uint32_t s2u(const void* p) {
    return (uint32_t)__cvta_generic_to_shared(p);
}
#define CP16(dst, src) \
    asm volatile("cp.async.cg.shared.global [%0], [%1], 16;" :: "r"(s2u(dst)), "l"(src))
#define CP_COMMIT() asm volatile("cp.async.commit_group;")
#define CP_WAIT(n)  asm volatile("cp.async.wait_group %0;" :: "n"(n))

// ---------------- weight pack: W[k][n] -> WpHL[mat][kp][n][2] ---------------
__global__ void pack_w_kernel(const float* __restrict__ W0, const float* __restrict__ W1,
                              const float* __restrict__ W2, const float* __restrict__ W3,
                              const float* __restrict__ W4) {
    int mat = blockIdx.y;
    const float* W = (mat == 0) ? W0 : (mat == 1) ? W1 : (mat == 2) ? W2
                   : (mat == 3) ? W3 : W4;
    int u = blockIdx.x * 256 + threadIdx.x;     // < 384*768
    int kp = u / CX, n = u - kp * CX;
    float w0 = W[(2 * kp) * CX + n];
    float w1 = W[(2 * kp + 1) * CX + n];
    uint32_t h, l;
    split2(w0, w1, h, l);
    *(uint2*)&g_WpHL[((size_t)mat * KP * CX + u) * 2] = make_uint2(h, l);
}

// ---------------- LayerNorm: writes interleaved hi/lo directly --------------
__global__ void ln_kernel(const float* __restrict__ x,
                          const float* __restrict__ gw,
                          const float* __restrict__ bw) {
    int row = blockIdx.x;
    int t = threadIdx.x;
    const float* xr = x + row * CX;
    float v0 = xr[t], v1 = xr[t + 256], v2 = xr[t + 512];
    float s = v0 + v1 + v2;
    float sq = v0 * v0 + v1 * v1 + v2 * v2;
    __shared__ float rs[8], rq[8];
    #pragma unroll
    for (int o = 16; o > 0; o >>= 1) {
        s  += __shfl_xor_sync(0xffffffffu, s, o);
        sq += __shfl_xor_sync(0xffffffffu, sq, o);
    }
    if ((t & 31) == 0) { rs[t >> 5] = s; rq[t >> 5] = sq; }
    __syncthreads();
    s  = rs[0] + rs[1] + rs[2] + rs[3] + rs[4] + rs[5] + rs[6] + rs[7];
    sq = rq[0] + rq[1] + rq[2] + rq[3] + rq[4] + rq[5] + rq[6] + rq[7];
    float mu  = s * (1.0f / CX);
    float inv = rsqrtf(sq * (1.0f / CX) - mu * mu + 1e-5f);
    if (t < 192) {
        float4 xv = *(const float4*)&xr[4 * t];
        float4 gv = *(const float4*)&gw[4 * t];
        float4 bv = *(const float4*)&bw[4 * t];
        float n0 = (xv.x - mu) * inv * gv.x + bv.x;
        float n1 = (xv.y - mu) * inv * gv.y + bv.y;
        float n2 = (xv.z - mu) * inv * gv.z + bv.z;
        float n3 = (xv.w - mu) * inv * gv.w + bv.w;
        uint32_t h0, l0, h1, l1;
        split2(n0, n1, h0, l0);
        split2(n2, n3, h1, l1);
        uint4 v; v.x = h0; v.y = l0; v.z = h1; v.w = l1;
        *(uint4*)&g_ApHL[((size_t)row * KP + 2 * t) * 2] = v;
    }
}

// ---------------- bf16x2 GEMM, interleaved hi/lo, cp.async 2-stage ----------
// C[2048 x cols] = A[2048x768] @ W[768 x cols]; C ~= AhBh + AhBl + AlBh
// hi/lo pairs adjacent in smem -> every fragment (hi,lo) is ONE LDS.64.
// A smem: [row][20 pairs] (16 data + 4 pad; 160B row stride, conflict-free)
// B smem: [kp][68 pairs]  (64 data + 4 pad; 68 == 4 mod 16 -> conflict-free)
// mode 0: A = packed xn, mats {0..3} = {Wq,Wk,Wv,Wg} (grid.x = 48)
// mode 1: A = packed wa, mat 4 = Wo, fp32 store to dst (grid.x = 12)
__global__ __launch_bounds__(128) void gemm_kernel(
    const float* __restrict__ bq, float* __restrict__ dst, int mode) {
    __shared__ uint32_t AsI[2][64 * 40];    // 64 rows x 20 pairs x 2 u32
    __shared__ uint32_t BsI[2][16 * 136];   // 16 kp x 68 pairs x 2 u32
    const uint32_t* AP = mode ? g_WaHL : g_ApHL;
    int m0 = blockIdx.y * 64;
    int gn = blockIdx.x * 64;
    int sel, n0w;
    if (mode == 0) { sel = gn / CX; n0w = gn - sel * CX; }
    else           { sel = 4;       n0w = gn; }
    const uint32_t* WP = g_WpHL + (size_t)sel * KP * CX * 2;

    int tid = threadIdx.x;
    int wp = tid >> 5, lane = tid & 31, g = lane >> 2, tig = lane & 3;
    int wm = wp >> 1, wn = wp & 1;

    float acc[2][4][4];
    #pragma unroll
    for (int a = 0; a < 2; a++)
        #pragma unroll
        for (int b = 0; b < 4; b++)
            #pragma unroll
            for (int c = 0; c < 4; c++) acc[a][b][c] = 0.f;

    auto issue = [&](int kb, int st) {
        #pragma unroll
        for (int i = 0; i < 4; i++) {       // A: 512 chunks of 16B (2 pairs)
            int c = tid + i * 128;
            int row = c >> 3, q2 = c & 7;
            CP16(&AsI[st][row * 40 + q2 * 4],
                 &AP[((size_t)(m0 + row) * KP + kb * 16 + q2 * 2) * 2]);
        }
        #pragma unroll
        for (int i = 0; i < 4; i++) {       // B: 512 chunks of 16B (2 n-pairs)
            int c = tid + i * 128;
            int kp = c >> 5, nq = (c & 31) * 2;
            CP16(&BsI[st][kp * 136 + nq * 2],
                 &WP[(((size_t)(kb * 16 + kp)) * CX + n0w + nq) * 2]);
        }
    };

    issue(0, 0);
    CP_COMMIT();
    for (int kb = 0; kb < 24; kb++) {
        int st = kb & 1;
        if (kb < 23) { issue(kb + 1, st ^ 1); CP_COMMIT(); CP_WAIT(1); }
        else         { CP_WAIT(0); }
        __syncthreads();
        #pragma unroll
        for (int ch = 0; ch < 2; ch++) {
            int base = ch * 8;
            uint32_t ah[2][4], al[2][4];
            #pragma unroll
            for (int mt = 0; mt < 2; mt++) {
                int rr = 32 * wm + 16 * mt + g;
                int o0 = (rr * 20 + base + tig) * 2;
                int o1 = ((rr + 8) * 20 + base + tig) * 2;
                uint2 v0 = *(const uint2*)&AsI[st][o0];
                uint2 v1 = *(const uint2*)&AsI[st][o1];
                uint2 v2 = *(const uint2*)&AsI[st][o0 + 8];
                uint2 v3 = *(const uint2*)&AsI[st][o1 + 8];
                ah[mt][0] = v0.x; ah[mt][1] = v1.x; ah[mt][2] = v2.x; ah[mt][3] = v3.x;
                al[mt][0] = v0.y; al[mt][1] = v1.y; al[mt][2] = v2.y; al[mt][3] = v3.y;
            }
            #pragma unroll
            for (int nt = 0; nt < 4; nt++) {
                int n = 32 * wn + 8 * nt + g;
                uint2 b0v = *(const uint2*)&BsI[st][((base + tig) * 68 + n) * 2];
                uint2 b1v = *(const uint2*)&BsI[st][((base + tig + 4) * 68 + n) * 2];
                uint32_t bh0 = b0v.x, bl0 = b0v.y;
                uint32_t bh1 = b1v.x, bl1 = b1v.y;
                #pragma unroll
                for (int mt = 0; mt < 2; mt++) {
                    mma16bf(acc[mt][nt][0], acc[mt][nt][1], acc[mt][nt][2], acc[mt][nt][3],
                            ah[mt][0], ah[mt][1], ah[mt][2], ah[mt][3], bl0, bl1);
                    mma16bf(acc[mt][nt][0], acc[mt][nt][1], acc[mt][nt][2], acc[mt][nt][3],
                            al[mt][0], al[mt][1], al[mt][2], al[mt][3], bh0, bh1);
                    mma16bf(acc[mt][nt][0], acc[mt][nt][1], acc[mt][nt][2], acc[mt][nt][3],
                            ah[mt][0], ah[mt][1], ah[mt][2], ah[mt][3], bh0, bh1);
                }
            }
        }
        __syncthreads();
    }
    const float qscale = 0.14433756729740643f;  // 48^-0.5
    #pragma unroll
    for (int mt = 0; mt < 2; mt++) {
        #pragma unroll
        for (int nt = 0; nt < 4; nt++) {
            int r0 = m0 + 32 * wm + 16 * mt + g;
            int cw = n0w + 32 * wn + 8 * nt + 2 * tig;
            #pragma unroll
            for (int i = 0; i < 4; i++) {
                int row = r0 + ((i >= 2) ? 8 : 0);
                int col = cw + (i & 1);
                float v = acc[mt][nt][i];
                if (sel == 4)      dst[row * CX + col] = v;
                else if (sel == 0) g_q[row * CX + col] = tf32r((v + bq[col]) * qscale);
                else if (sel == 1) g_k[row * CX + col] = tf32r(v);
                else if (sel == 2) g_v[row * CX + col] = tf32r(v);
                else               g_gate[row * CX + col] = 1.f / (1.f + __expf(-v));
            }
        }
    }
}

// ---------------- attention: EXACT R10 design (best measured: 177us) --------
// 4 warps x 16 q-rows, 32-key double-buffered tiles, fixed-max softmax.
__global__ __launch_bounds__(128, 5) void attn_kernel(const float* __restrict__ pair,
                                                      float* __restrict__ out_wa) {
    __shared__ float Ks[2][32 * 52];
    __shared__ float Vs[2][32 * 56];
    __shared__ float Ps[64 * 36];
    int qt = blockIdx.x, h = blockIdx.y;
    int q0 = qt * 64, hc0 = h * DH;
    int tid = threadIdx.x, w = tid >> 5, lane = tid & 31, g = lane >> 2, tig = lane & 3;

    // stage Q (64x48, stride 52) through the Ks region; lift A-fragments
    float* Qstage = &Ks[0][0];   // 2*32*52 = 64*52 floats
    #pragma unroll
    for (int i = 0; i < 6; i++) {
        int f4 = tid + i * 128;
        int r = f4 / 12, c4 = f4 % 12;
        *(float4*)&Qstage[r * 52 + c4 * 4] =
            *(const float4*)&g_q[(size_t)(q0 + r) * CX + hc0 + c4 * 4];
    }
    __syncthreads();
    uint32_t qa[6][4];
    int qrow = 16 * w + g;
    #pragma unroll
    for (int ks = 0; ks < 6; ks++) {
        qa[ks][0] = __float_as_uint(Qstage[qrow * 52 + ks * 8 + tig]);
        qa[ks][1] = __float_as_uint(Qstage[(qrow + 8) * 52 + ks * 8 + tig]);
        qa[ks][2] = __float_as_uint(Qstage[qrow * 52 + ks * 8 + tig + 4]);
        qa[ks][3] = __float_as_uint(Qstage[(qrow + 8) * 52 + ks * 8 + tig + 4]);
    }
    __syncthreads();

    float l0 = 0.f, l1 = 0.f;
    float o[6][4];
    #pragma unroll
    for (int d = 0; d < 6; d++)
        #pragma unroll
        for (int i = 0; i < 4; i++) o[d][i] = 0.f;

    const float* ph = pair + (size_t)h * N_TOKS * N_TOKS;

    auto issueKV = [&](int kt, int st) {
        int k0 = kt * 32;
        #pragma unroll
        for (int i = 0; i < 3; i++) {
            int f4 = tid + i * 128;
            int r = f4 / 12, c4 = f4 % 12;
            CP16(&Ks[st][r * 52 + c4 * 4], &g_k[(size_t)(k0 + r) * CX + hc0 + c4 * 4]);
            CP16(&Vs[st][r * 56 + c4 * 4], &g_v[(size_t)(k0 + r) * CX + hc0 + c4 * 4]);
        }
    };
    issueKV(0, 0);
    CP_COMMIT();

    for (int kt = 0; kt < 64; kt++) {
        int st = kt & 1;
        int k0 = kt * 32;

        // pair bias into S accumulators (LDG latency overlaps copy-wait+barrier)
        float s[4][4];
        #pragma unroll
        for (int nt = 0; nt < 4; nt++) {
            float2 p0 = *(const float2*)&ph[(size_t)(q0 + qrow) * N_TOKS + k0 + 8 * nt + 2 * tig];
            float2 p1 = *(const float2*)&ph[(size_t)(q0 + qrow + 8) * N_TOKS + k0 + 8 * nt + 2 * tig];
            s[nt][0] = p0.x; s[nt][1] = p0.y; s[nt][2] = p1.x; s[nt][3] = p1.y;
        }

        if (kt < 63) { issueKV(kt + 1, st ^ 1); CP_COMMIT(); CP_WAIT(1); }
        else         { CP_WAIT(0); }
        __syncthreads();

        #pragma unroll
        for (int ks = 0; ks < 6; ks++) {
            #pragma unroll
            for (int nt = 0; nt < 4; nt++) {
                uint32_t b0 = __float_as_uint(Ks[st][(8 * nt + g) * 52 + ks * 8 + tig]);
                uint32_t b1 = __float_as_uint(Ks[st][(8 * nt + g) * 52 + ks * 8 + tig + 4]);
                mma8(s[nt][0], s[nt][1], s[nt][2], s[nt][3],
                     qa[ks][0], qa[ks][1], qa[ks][2], qa[ks][3], b0, b1);
            }
        }

        // fixed-max softmax: logits = pair + scaled qk, bounded << 18
        float ls0 = 0.f, ls1 = 0.f;
        #pragma unroll
        for (int nt = 0; nt < 4; nt++) {
            float p00 = __expf(s[nt][0] - 18.f), p01 = __expf(s[nt][1] - 18.f);
            float p10 = __expf(s[nt][2] - 18.f), p11 = __expf(s[nt][3] - 18.f);
            ls0 += p00 + p01; ls1 += p10 + p11;
            int col = 8 * nt + 2 * tig;
            *(float2*)&Ps[(16 * w + g) * 36 + col]     = make_float2(tf32r(p00), tf32r(p01));
            *(float2*)&Ps[(16 * w + g + 8) * 36 + col] = make_float2(tf32r(p10), tf32r(p11));
        }
        l0 += ls0; l1 += ls1;
        __syncwarp();

        // O += P @ V
        #pragma unroll
        for (int ks = 0; ks < 4; ks++) {
            uint32_t a0 = __float_as_uint(Ps[(16 * w + g) * 36 + ks * 8 + tig]);
            uint32_t a1 = __float_as_uint(Ps[(16 * w + g + 8) * 36 + ks * 8 + tig]);
            uint32_t a2 = __float_as_uint(Ps[(16 * w + g) * 36 + ks * 8 + tig + 4]);
            uint32_t a3 = __float_as_uint(Ps[(16 * w + g + 8) * 36 + ks * 8 + tig + 4]);
            #pragma unroll
            for (int nt = 0; nt < 6; nt++) {
                uint32_t b0 = __float_as_uint(Vs[st][(ks * 8 + tig) * 56 + 8 * nt + g]);
                uint32_t b1 = __float_as_uint(Vs[st][(ks * 8 + tig + 4) * 56 + 8 * nt + g]);
                mma8(o[nt][0], o[nt][1], o[nt][2], o[nt][3], a0, a1, a2, a3, b0, b1);
            }
        }
        __syncthreads();   // release stage st before next iteration overwrites it
    }

    // butterfly across the 4 tig-lanes gives the full-row denominator
    l0 += __shfl_xor_sync(0xffffffffu, l0, 1);
    l0 += __shfl_xor_sync(0xffffffffu, l0, 2);
    l1 += __shfl_xor_sync(0xffffffffu, l1, 1);
    l1 += __shfl_xor_sync(0xffffffffu, l1, 2);

    // epilogue: normalize, gate, write wa (fp32 out) + interleaved hi/lo pack
    float inv0 = 1.f / l0, inv1 = 1.f / l1;
    int r0 = q0 + 16 * w + g, r1 = r0 + 8;
    #pragma unroll
    for (int nt = 0; nt < 6; nt++) {
        int cw = hc0 + 8 * nt + 2 * tig;
        float2 gt0 = *(const float2*)&g_gate[r0 * CX + cw];
        float2 gt1 = *(const float2*)&g_gate[r1 * CX + cw];
        float v00 = o[nt][0] * inv0 * gt0.x;
        float v01 = o[nt][1] * inv0 * gt0.y;
        float v10 = o[nt][2] * inv1 * gt1.x;
        float v11 = o[nt][3] * inv1 * gt1.y;
        *(float2*)&out_wa[r0 * CX + cw] = make_float2(v00, v01);
        *(float2*)&out_wa[r1 * CX + cw] = make_float2(v10, v11);
        uint32_t hh, ll;
        split2(v00, v01, hh, ll);
        *(uint2*)&g_WaHL[((size_t)r0 * KP + (cw >> 1)) * 2] = make_uint2(hh, ll);
        split2(v10, v11, hh, ll);
        *(uint2*)&g_WaHL[((size_t)r1 * KP + (cw >> 1)) * 2] = make_uint2(hh, ll);
    }
}

// ---------------- launch -----------------------------------------------------
extern "C" void kernel_launch(void* const* d_in, const int* in_sizes, int n_in,
                              void* d_out, int out_size) {
    int ip = 2;
    for (int i = 0; i < n_in; i++)
        if (in_sizes[i] == NHEAD * N_TOKS * N_TOKS) { ip = i; break; }
    int sh = ip - 2;

    const float* x    = (const float*)d_in[0];
    const float* pair = (const float*)d_in[ip];
    const float* ln_g = (const float*)d_in[3 + sh];
    const float* ln_b = (const float*)d_in[4 + sh];
    const float* Wq   = (const float*)d_in[5 + sh];
    const float* bq   = (const float*)d_in[6 + sh];
    const float* Wk   = (const float*)d_in[7 + sh];
    const float* Wv   = (const float*)d_in[8 + sh];
    const float* Wg   = (const float*)d_in[9 + sh];
    const float* Wo   = (const float*)d_in[10 + sh];

    float* out = (float*)d_out;
    const int NC = N_TOKS * CX;
    float* wa_dst  = out;
    float* out_dst = (out_size >= 2 * NC) ? (out + NC) : out;

    pack_w_kernel<<<dim3(1152, 5), 256>>>(Wq, Wk, Wv, Wg, Wo);
    ln_kernel<<<N_TOKS, 256>>>(x, ln_g, ln_b);
    gemm_kernel<<<dim3(48, 32), 128>>>(bq, nullptr, 0);
    attn_kernel<<<dim3(32, 16), 128>>>(pair, wa_dst);
    gemm_kernel<<<dim3(12, 32), 128>>>(bq, out_dst, 1);
}